// round 3
// baseline (speedup 1.0000x reference)
#include <cuda_runtime.h>
#include <cuda_bf16.h>

// Problem constants (fixed by reference_code)
#define HH 768
#define WW 768
#define BB 9
#define CC 3
#define NS 100          // N_SAMPLES
#define MM 13           // offsets with dy^2+dx^2 <= 4
#define DD 27           // PATCH*PATCH*C
#define DPAD 29         // padded stride (odd -> conflict-free vs 32 banks)
// scale = (1/T^2) / (K * B * NS) = 4 / (8*9*100); divide by counts[n] per block
#define BASE_SCALE (4.0f / (8.0f * 9.0f * 100.0f))

__device__ float g_partials[NS];

__device__ __constant__ int c_offy[MM] = {-2,-1,-1,-1, 0, 0, 0, 0, 0, 1, 1, 1, 2};
__device__ __constant__ int c_offx[MM] = { 0,-1, 0, 1,-2,-1, 0, 1, 2,-1, 0, 1, 0};

__global__ __launch_bounds__(256)
void anchor_kernel(const float* __restrict__ latents,
                   const int*   __restrict__ anchor_idx) {
    __shared__ float sh[BB * MM * DPAD];     // 117 normalized patch vectors
    __shared__ int   s_valid[MM];
    __shared__ float s_wsum[8];

    const int n   = blockIdx.x;
    const int tid = threadIdx.x;
    const int a   = anchor_idx[n];
    const int ay  = a / WW;
    const int ax  = a - ay * WW;

    if (tid < MM) {
        const int ny = ay + c_offy[tid];
        const int nx = ax + c_offx[tid];
        s_valid[tid] = (ny >= 0 && ny < HH && nx >= 0 && nx < WW) ? 1 : 0;
    }

    // --- Phase 1: build 117 normalized patch vectors (one per thread) ---
    if (tid < BB * MM) {
        const int j = tid / MM;
        const int m = tid - j * MM;
        int py = ay + c_offy[m];
        int px = ax + c_offx[m];
        // clip (matches jnp.clip; invalid offsets are masked later anyway)
        py = min(max(py, 0), HH - 1);
        px = min(max(px, 0), WW - 1);

        const float* base = latents + (size_t)j * (HH * WW * CC);
        float v[DD];
        float ss = 0.0f;
        #pragma unroll
        for (int ky = -1; ky <= 1; ky++) {
            const int yy = min(max(py + ky, 0), HH - 1);
            #pragma unroll
            for (int kx = -1; kx <= 1; kx++) {
                const int xx = min(max(px + kx, 0), WW - 1);
                const float* p = base + ((size_t)yy * WW + xx) * CC;
                #pragma unroll
                for (int c = 0; c < CC; c++) {
                    const float f = p[c];
                    v[((ky + 1) * 3 + (kx + 1)) * 3 + c] = f;
                    ss += f * f;
                }
            }
        }
        const float inv = 1.0f / fmaxf(sqrtf(ss), 1e-12f);
        float* dst = &sh[tid * DPAD];
        #pragma unroll
        for (int d = 0; d < DD; d++) dst[d] = v[d] * inv;
    }
    __syncthreads();

    // counts[n] = number of valid offsets for this anchor
    int cnt = 0;
    #pragma unroll
    for (int m = 0; m < MM; m++) cnt += s_valid[m];

    // --- Phase 2: sum over (b, j!=b, valid m) of (anchor_b . neigh_{j,m})^2 ---
    float acc = 0.0f;
    for (int pid = tid; pid < BB * BB * MM; pid += blockDim.x) {
        const int b   = pid / (BB * MM);
        const int rem = pid - b * (BB * MM);
        const int j   = rem / MM;
        const int m   = rem - j * MM;
        if (b == j || !s_valid[m]) continue;
        const float* av = &sh[(b * MM + 6) * DPAD];  // offset 6 == (0,0) == anchor
        const float* nv = &sh[rem * DPAD];
        float d = 0.0f;
        #pragma unroll
        for (int k = 0; k < DD; k++) d = fmaf(av[k], nv[k], d);
        acc += d * d;
    }

    // --- Block reduction (deterministic tree) ---
    #pragma unroll
    for (int o = 16; o > 0; o >>= 1)
        acc += __shfl_down_sync(0xFFFFFFFFu, acc, o);
    if ((tid & 31) == 0) s_wsum[tid >> 5] = acc;
    __syncthreads();
    if (tid == 0) {
        float s = 0.0f;
        #pragma unroll
        for (int w = 0; w < 8; w++) s += s_wsum[w];
        g_partials[n] = s * (BASE_SCALE / (float)cnt);
    }
}

__global__ __launch_bounds__(128)
void finish_kernel(float* __restrict__ out) {
    __shared__ float s_wsum[4];
    const int tid = threadIdx.x;
    float acc = (tid < NS) ? g_partials[tid] : 0.0f;
    #pragma unroll
    for (int o = 16; o > 0; o >>= 1)
        acc += __shfl_down_sync(0xFFFFFFFFu, acc, o);
    if ((tid & 31) == 0) s_wsum[tid >> 5] = acc;
    __syncthreads();
    if (tid == 0) {
        float s = 0.0f;
        #pragma unroll
        for (int w = 0; w < 4; w++) s += s_wsum[w];
        out[0] = s;
    }
}

extern "C" void kernel_launch(void* const* d_in, const int* in_sizes, int n_in,
                              void* d_out, int out_size) {
    const float* latents    = (const float*)d_in[0];
    const int*   anchor_idx = (const int*)d_in[1];
    float*       out        = (float*)d_out;

    anchor_kernel<<<NS, 256>>>(latents, anchor_idx);
    finish_kernel<<<1, 128>>>(out);
}

// round 4
// speedup vs baseline: 1.0239x; 1.0239x over previous
#include <cuda_runtime.h>
#include <cuda_bf16.h>

// Problem constants (fixed by reference_code)
#define HH 768
#define WW 768
#define BB 9
#define CC 3
#define NS 100          // N_SAMPLES
#define MM 13           // offsets with dy^2+dx^2 <= 4
#define DD 27           // PATCH*PATCH*C
#define DPAD 29         // padded stride (odd -> conflict-free vs 32 banks)
// scale = (1/T^2) / (K * B * NS) = 4 / (8*9*100); divide by counts[n] per block
#define BASE_SCALE (4.0f / (8.0f * 9.0f * 100.0f))

__device__ float        g_partials[NS];
__device__ unsigned int g_done = 0;    // completion counter; reset by last block each call

__device__ __constant__ int c_offy[MM] = {-2,-1,-1,-1, 0, 0, 0, 0, 0, 1, 1, 1, 2};
__device__ __constant__ int c_offx[MM] = { 0,-1, 0, 1,-2,-1, 0, 1, 2,-1, 0, 1, 0};

__global__ __launch_bounds__(256)
void fused_kernel(const float* __restrict__ latents,
                  const int*   __restrict__ anchor_idx,
                  float*       __restrict__ out) {
    __shared__ float sh[BB * MM * DPAD];     // 117 normalized patch vectors
    __shared__ int   s_valid[MM];
    __shared__ float s_wsum[8];
    __shared__ bool  s_is_last;

    const int n   = blockIdx.x;
    const int tid = threadIdx.x;
    const int a   = anchor_idx[n];
    const int ay  = a / WW;
    const int ax  = a - ay * WW;

    if (tid < MM) {
        const int ny = ay + c_offy[tid];
        const int nx = ax + c_offx[tid];
        s_valid[tid] = (ny >= 0 && ny < HH && nx >= 0 && nx < WW) ? 1 : 0;
    }

    // --- Phase 1: build 117 normalized patch vectors (one per thread) ---
    if (tid < BB * MM) {
        const int j = tid / MM;
        const int m = tid - j * MM;
        int py = ay + c_offy[m];
        int px = ax + c_offx[m];
        py = min(max(py, 0), HH - 1);
        px = min(max(px, 0), WW - 1);

        const float* base = latents + (size_t)j * (HH * WW * CC);
        float v[DD];
        float ss = 0.0f;
        #pragma unroll
        for (int ky = -1; ky <= 1; ky++) {
            const int yy = min(max(py + ky, 0), HH - 1);
            #pragma unroll
            for (int kx = -1; kx <= 1; kx++) {
                const int xx = min(max(px + kx, 0), WW - 1);
                const float* p = base + ((size_t)yy * WW + xx) * CC;
                #pragma unroll
                for (int c = 0; c < CC; c++) {
                    const float f = p[c];
                    v[((ky + 1) * 3 + (kx + 1)) * 3 + c] = f;
                    ss += f * f;
                }
            }
        }
        const float inv = 1.0f / fmaxf(sqrtf(ss), 1e-12f);
        float* dst = &sh[tid * DPAD];
        #pragma unroll
        for (int d = 0; d < DD; d++) dst[d] = v[d] * inv;
    }
    __syncthreads();

    int cnt = 0;
    #pragma unroll
    for (int m = 0; m < MM; m++) cnt += s_valid[m];

    // --- Phase 2: sum over (b, j!=b, valid m) of (anchor_b . neigh_{j,m})^2 ---
    float acc = 0.0f;
    for (int pid = tid; pid < BB * BB * MM; pid += blockDim.x) {
        const int b   = pid / (BB * MM);
        const int rem = pid - b * (BB * MM);
        const int j   = rem / MM;
        const int m   = rem - j * MM;
        if (b == j || !s_valid[m]) continue;
        const float* av = &sh[(b * MM + 6) * DPAD];  // offset 6 == (0,0) == anchor
        const float* nv = &sh[rem * DPAD];
        float d = 0.0f;
        #pragma unroll
        for (int k = 0; k < DD; k++) d = fmaf(av[k], nv[k], d);
        acc += d * d;
    }

    // --- Block reduction (deterministic tree) ---
    #pragma unroll
    for (int o = 16; o > 0; o >>= 1)
        acc += __shfl_down_sync(0xFFFFFFFFu, acc, o);
    if ((tid & 31) == 0) s_wsum[tid >> 5] = acc;
    __syncthreads();

    if (tid == 0) {
        float s = 0.0f;
        #pragma unroll
        for (int w = 0; w < 8; w++) s += s_wsum[w];
        g_partials[n] = s * (BASE_SCALE / (float)cnt);
        __threadfence();                       // make partial visible before counter bump
        unsigned int prev = atomicAdd(&g_done, 1u);
        s_is_last = (prev == NS - 1);
    }
    __syncthreads();

    // --- Last block reduces all partials in fixed order (deterministic) ---
    if (s_is_last) {
        __threadfence();                       // acquire side: see all partials
        if (tid < 32) {
            const volatile float* gp = g_partials;
            float t = 0.0f;
            // fixed-order: lane i sums gp[i], gp[i+32], gp[i+64], gp[i+96]
            for (int k = tid; k < NS; k += 32) t += gp[k];
            #pragma unroll
            for (int o = 16; o > 0; o >>= 1)
                t += __shfl_down_sync(0xFFFFFFFFu, t, o);
            if (tid == 0) {
                out[0] = t;
                g_done = 0;                    // reset for next graph replay
            }
        }
    }
}

extern "C" void kernel_launch(void* const* d_in, const int* in_sizes, int n_in,
                              void* d_out, int out_size) {
    const float* latents    = (const float*)d_in[0];
    const int*   anchor_idx = (const int*)d_in[1];
    float*       out        = (float*)d_out;

    fused_kernel<<<NS, 256>>>(latents, anchor_idx, out);
}